// round 16
// baseline (speedup 1.0000x reference)
#include <cuda_runtime.h>
#include <cuda_bf16.h>
#include <cuda_fp8.h>
#include <math.h>
#include <stdint.h>

#define Vv 32000
#define Ee 512
#define Hh 1024
#define Bb 16
#define Ss 128
#define Kk 15

#define ASCALE 128.0f
#define BSCALE 256.0f

// ------------------------- device scratch (no allocs allowed) -------------------------
__device__ float g_G[Ss * Bb * Hh];               // [s][b][h]
__device__ __nv_bfloat16 g_Hhi[2][Bb * Hh];
__device__ __nv_bfloat16 g_Hlo[2][Bb * Hh];
__device__ float g_topic[Vv];
__device__ unsigned g_epoch;                      // bumped each launch (init_h)
__device__ unsigned g_flags[64 * 32];             // per-rnn-CTA flag, 1 per 128B line
__device__ unsigned g_tile;                       // dec tile queue head (reset each launch)
__device__ unsigned g_conv;                       // B-conversion done counter (reset each launch)
// fp8 decoder operands
__device__ uint8_t g_A8[2048 * 1024];             // [m = s*16+b][k]  (h * 128, e4m3)
__device__ uint8_t g_B8[(size_t)Vv * 1024];       // [v][k]           (W_dec * 256, e4m3)
// pre-split bf16 operands for embed GEMM
__device__ __nv_bfloat16 g_EAhi[2048 * Ee];
__device__ __nv_bfloat16 g_EAlo[2048 * Ee];
__device__ __nv_bfloat16 g_EBhi[Hh * Ee];
__device__ __nv_bfloat16 g_EBlo[Hh * Ee];

// ------------------------- PTX helpers -------------------------
__device__ __forceinline__ uint32_t smem_u32(const void* p) {
    uint32_t a;
    asm("{ .reg .u64 t; cvta.to.shared.u64 t, %1; cvt.u32.u64 %0, t; }" : "=r"(a) : "l"(p));
    return a;
}
__device__ __forceinline__ void cp_async16(uint32_t dst, const void* src) {
    asm volatile("cp.async.cg.shared.global [%0], [%1], 16;" :: "r"(dst), "l"(src) : "memory");
}
__device__ __forceinline__ void cp_commit() { asm volatile("cp.async.commit_group;" ::: "memory"); }

__device__ __forceinline__ void ldsm4(uint32_t* r, uint32_t addr) {
    asm volatile("ldmatrix.sync.aligned.m8n8.x4.shared.b16 {%0,%1,%2,%3}, [%4];"
                 : "=r"(r[0]), "=r"(r[1]), "=r"(r[2]), "=r"(r[3]) : "r"(addr));
}
__device__ __forceinline__ void mma16816(float* c, const uint32_t* a, uint32_t b0, uint32_t b1) {
    asm volatile("mma.sync.aligned.m16n8k16.row.col.f32.bf16.bf16.f32 "
                 "{%0,%1,%2,%3}, {%4,%5,%6,%7}, {%8,%9}, {%0,%1,%2,%3};"
                 : "+f"(c[0]), "+f"(c[1]), "+f"(c[2]), "+f"(c[3])
                 : "r"(a[0]), "r"(a[1]), "r"(a[2]), "r"(a[3]), "r"(b0), "r"(b1));
}
__device__ __forceinline__ void mma16832f8(float* c, const uint32_t* a, uint32_t b0, uint32_t b1) {
    asm volatile("mma.sync.aligned.m16n8k32.row.col.f32.e4m3.e4m3.f32 "
                 "{%0,%1,%2,%3}, {%4,%5,%6,%7}, {%8,%9}, {%0,%1,%2,%3};"
                 : "+f"(c[0]), "+f"(c[1]), "+f"(c[2]), "+f"(c[3])
                 : "r"(a[0]), "r"(a[1]), "r"(a[2]), "r"(a[3]), "r"(b0), "r"(b1));
}
__device__ __forceinline__ uint8_t to_e4m3(float x) {
    return (uint8_t)__nv_cvt_float_to_fp8(x, __NV_SATFINITE, __NV_E4M3);
}
__device__ __forceinline__ void st_release(unsigned* p, unsigned v) {
    asm volatile("st.release.gpu.global.u32 [%0], %1;" :: "l"(p), "r"(v) : "memory");
}
__device__ __forceinline__ unsigned ld_relaxed(const unsigned* p) {
    unsigned v;
    asm volatile("ld.relaxed.gpu.global.u32 %0, [%1];" : "=r"(v) : "l"(p));
    return v;
}
__device__ __forceinline__ unsigned ld_acquire(const unsigned* p) {
    unsigned v;
    asm volatile("ld.acquire.gpu.global.u32 %0, [%1];" : "=r"(v) : "l"(p) : "memory");
    return v;
}
__device__ __forceinline__ uint32_t ldcg_u32(const void* p) {
    uint32_t v;
    asm volatile("ld.global.cg.u32 %0, [%1];" : "=r"(v) : "l"(p));
    return v;
}

// ------------------------- tiny kernels -------------------------
__global__ void topic_kernel(const float* __restrict__ beta, const float* __restrict__ theta) {
    int v = blockIdx.x * 256 + threadIdx.x;
    if (v < Vv) {
        float s = 0.f;
#pragma unroll
        for (int k = 0; k < Kk; k++) s += theta[k] * beta[k * Vv + v];
        g_topic[v] = s;
    }
}
__global__ void init_h_kernel(const float* __restrict__ hidden) {
    int i = blockIdx.x * 256 + threadIdx.x;
    if (i < Bb * Hh) {
        float x = hidden[i];
        __nv_bfloat16 hi = __float2bfloat16(x);
        g_Hhi[0][i] = hi;
        g_Hlo[0][i] = __float2bfloat16(x - __bfloat162float(hi));
    }
    if (i == 0) { g_epoch = g_epoch + 1; g_tile = 0; g_conv = 0; }
}
// gather + split W_emb rows -> EA slabs
__global__ void convA_emb_kernel(const int* __restrict__ ids,
                                 const float* __restrict__ W_emb) {
    int i = blockIdx.x * 256 + threadIdx.x;   // 2048*512
    int m = i >> 9, k = i & 511;
    int row = ids[(m & 15) * Ss + (m >> 4)];
    float x = W_emb[(size_t)row * Ee + k];
    __nv_bfloat16 hi = __float2bfloat16(x);
    g_EAhi[i] = hi;
    g_EAlo[i] = __float2bfloat16(x - __bfloat162float(hi));
}
// split W_ih -> EB slabs
__global__ void convWih_kernel(const float* __restrict__ W_ih) {
    int i = blockIdx.x * 256 + threadIdx.x;   // 1024*512
    float x = W_ih[i];
    __nv_bfloat16 hi = __float2bfloat16(x);
    g_EBhi[i] = hi;
    g_EBlo[i] = __float2bfloat16(x - __bfloat162float(hi));
}

// ------------------------- embed GEMM: pipelined bf16, 3-term K-concat ---------------
#define EMB_ASZ 16384
#define EMB_BSZ 16384
#define EMB_STG (EMB_ASZ + EMB_BSZ)
#define EMB_SMEM (3 * EMB_STG + 1024)

__device__ __forceinline__ void emb_load_stage(uint32_t sb, int stg, int ki,
                                               int bm, int bn, int tid) {
    const int t = ki >> 3, kc = ki & 7;
    const __nv_bfloat16* sA = (t == 1) ? g_EAlo : g_EAhi;
    const __nv_bfloat16* sB = (t == 2) ? g_EBlo : g_EBhi;
    const __nv_bfloat16* gA = sA + (size_t)bm * Ee + kc * 64;
    const __nv_bfloat16* gB = sB + (size_t)bn * Ee + kc * 64;
    uint32_t base = sb + stg * EMB_STG;
#pragma unroll
    for (int i = 0; i < 4; i++) {
        int c = tid + i * 256;
        int r = c >> 3, cc = c & 7;
        cp_async16(base + r * 128 + (((cc ^ (r & 7)) & 7) << 4),
                   gA + (size_t)r * Ee + cc * 8);
    }
#pragma unroll
    for (int i = 0; i < 4; i++) {
        int c = tid + i * 256;
        int r = c >> 3, cc = c & 7;
        cp_async16(base + EMB_ASZ + r * 128 + (((cc ^ (r & 7)) & 7) << 4),
                   gB + (size_t)r * Ee + cc * 8);
    }
}

__global__ __launch_bounds__(256, 1) void embed_gemm(const float* __restrict__ b_ih,
                                                     const float* __restrict__ b_hh) {
    extern __shared__ __align__(16) char esm[];
    const int tid = threadIdx.x;
    const int wid = tid >> 5;
    const int lane = tid & 31;
    const int wm = wid & 1;
    const int wn = wid >> 1;
    const int bm = blockIdx.x * 128;
    const int bn = blockIdx.y * 128;
    uint32_t sb = (smem_u32(esm) + 1023) & ~1023u;

    float acc[4][4][4];
#pragma unroll
    for (int i = 0; i < 4; i++)
#pragma unroll
        for (int j = 0; j < 4; j++)
#pragma unroll
            for (int q = 0; q < 4; q++) acc[i][j][q] = 0.f;

    const int arow = wm * 64 + (lane & 15);
    const int ach = lane >> 4;
    const int as = arow & 7;
    const int brow = wn * 32 + ((lane >> 4) << 3) + (lane & 7);
    const int bch = (lane >> 3) & 1;
    const int bs = brow & 7;

    emb_load_stage(sb, 0, 0, bm, bn, tid); cp_commit();
    emb_load_stage(sb, 1, 1, bm, bn, tid); cp_commit();

    for (int ki = 0; ki < 24; ki++) {
        const int cur = ki % 3;
        if (ki + 2 < 24) {
            emb_load_stage(sb, (ki + 2) % 3, ki + 2, bm, bn, tid); cp_commit();
            asm volatile("cp.async.wait_group 2;" ::: "memory");
        } else if (ki + 1 < 24) {
            asm volatile("cp.async.wait_group 1;" ::: "memory");
        } else {
            asm volatile("cp.async.wait_group 0;" ::: "memory");
        }
        __syncthreads();

        const uint32_t aB = sb + cur * EMB_STG + arow * 128;
        const uint32_t bB = sb + cur * EMB_STG + EMB_ASZ + brow * 128;
#pragma unroll
        for (int k16 = 0; k16 < 4; k16++) {
            uint32_t af[4][4], bf[2][4];
            const uint32_t acs = ((uint32_t)((k16 * 2 + ach) ^ as)) << 4;
            const uint32_t bcs = ((uint32_t)((k16 * 2 + bch) ^ bs)) << 4;
#pragma unroll
            for (int mi = 0; mi < 4; mi++) ldsm4(af[mi], aB + mi * 2048 + acs);
#pragma unroll
            for (int ni2 = 0; ni2 < 2; ni2++) ldsm4(bf[ni2], bB + ni2 * 2048 + bcs);
#pragma unroll
            for (int mi = 0; mi < 4; mi++)
#pragma unroll
                for (int ni = 0; ni < 4; ni++)
                    mma16816(acc[mi][ni], af[mi], bf[ni >> 1][(ni & 1) * 2],
                             bf[ni >> 1][(ni & 1) * 2 + 1]);
        }
        __syncthreads();
    }

#pragma unroll
    for (int ni = 0; ni < 4; ni++) {
        int n0 = bn + wn * 32 + ni * 8 + (lane & 3) * 2;
        float2 bi = *(const float2*)(b_ih + n0);
        float2 bh = *(const float2*)(b_hh + n0);
        float2 bb = make_float2(bi.x + bh.x, bi.y + bh.y);
#pragma unroll
        for (int mi = 0; mi < 4; mi++) {
            int m0 = bm + wm * 64 + mi * 16 + (lane >> 2);
            float2 o0 = make_float2(acc[mi][ni][0] + bb.x, acc[mi][ni][1] + bb.y);
            float2 o1 = make_float2(acc[mi][ni][2] + bb.x, acc[mi][ni][3] + bb.y);
            *(float2*)(g_G + (size_t)m0 * Hh + n0) = o0;
            *(float2*)(g_G + (size_t)(m0 + 8) * Hh + n0) = o1;
        }
    }
}

// ------------------------- fused persistent kernel: rnn + dec -------------------------
#define RNN_NB 64
#define CMB_NB 148
#define N_TILES (16 * 125)
#define WHI_OFF 0
#define WLO_OFF 32768
#define RNN_RED_OFF 131072
#define DEC_ASZ 16384
#define DEC_BSZ 32768
#define DEC_STG (DEC_ASZ + DEC_BSZ)
#define FUSED_SMEM (3 * DEC_STG + 1024)

// ---- rnn role: per-warp dataflow, W frags in registers, h frags direct from L2 ----
__device__ void rnn_role(char* rsm, const float* __restrict__ W_hh,
                         float* __restrict__ out, unsigned base) {
    float* red = (float*)(rsm + RNN_RED_OFF);
    const int tid = threadIdx.x;
    const int wid = tid >> 5;
    const int lane = tid & 31;
    const int n0 = blockIdx.x * 16;

    // build W hi/lo slabs in SMEM (once)
#pragma unroll
    for (int i = 0; i < 8; i++) {
        int c = tid + i * 256;
        int r = c >> 7, kc = c & 127;
        const float* src = W_hh + (size_t)(n0 + r) * Hh + kc * 8;
        float4 v0 = *(const float4*)src;
        float4 v1 = *(const float4*)(src + 4);
        float x[8] = {v0.x, v0.y, v0.z, v0.w, v1.x, v1.y, v1.z, v1.w};
        __nv_bfloat16 hi[8], lo[8];
#pragma unroll
        for (int q = 0; q < 8; q++) {
            hi[q] = __float2bfloat16(x[q]);
            lo[q] = __float2bfloat16(x[q] - __bfloat162float(hi[q]));
        }
        uint32_t off = r * 2048 + (((kc ^ (r & 7)) & 127) << 4);
        *(uint4*)(rsm + WHI_OFF + off) = *(uint4*)hi;
        *(uint4*)(rsm + WLO_OFF + off) = *(uint4*)lo;
    }
    __syncthreads();

    const int brow = ((lane >> 4) << 3) + (lane & 7);
    const int bch = (lane >> 3) & 1;
    const int crow = lane >> 2, ccol = (lane & 3) * 2;
    const int rb = tid >> 4, rn = tid & 15;
    const uint32_t smb = smem_u32(rsm);
    const unsigned* wfp = &g_flags[(wid * 8 + (lane & 7)) * 32];

    // preload W fragments into registers (loop-invariant)
    uint32_t wh[8][4], wl[8][4];
#pragma unroll
    for (int jj = 0; jj < 8; jj++) {
        int cj = (wid * 8 + jj) * 2;
        uint32_t sw = ((((cj + bch) ^ (brow & 7)) & 127) << 4);
        ldsm4(wh[jj], smb + WHI_OFF + brow * 2048 + sw);
        ldsm4(wl[jj], smb + WLO_OFF + brow * 2048 + sw);
    }

    // h fragment byte offsets (A-frag layout of m16n8k16, rows = batch, cols = k)
    const uint32_t o0 = (uint32_t)(lane >> 2) * 2048 + (uint32_t)(lane & 3) * 4;
    const uint32_t o8 = o0 + 8 * 2048;
    const uint32_t kb0 = (uint32_t)wid * 256;           // byte offset of this warp's k-slab

    for (int s = 0; s < Ss; s++) {
        const int cur = s & 1;
        float gval = __ldcg(&g_G[(size_t)s * (Bb * Hh) + rb * Hh + n0 + rn]);

        if (s > 0) {
            if (lane < 8) {
                unsigned need = base + (unsigned)s;
                while (ld_relaxed(wfp) < need) { }
                (void)ld_acquire(wfp);
            }
            __syncwarp();
        }

        // direct L2 loads of h fragments (L1 bypass — ld.cg)
        const char* hhc = (const char*)g_Hhi[cur];
        const char* hlc = (const char*)g_Hlo[cur];
        uint32_t ah[8][4], al[8][4];
#pragma unroll
        for (int jj = 0; jj < 8; jj++) {
            uint32_t kb = kb0 + (uint32_t)jj * 32;
            ah[jj][0] = ldcg_u32(hhc + o0 + kb);
            ah[jj][1] = ldcg_u32(hhc + o8 + kb);
            ah[jj][2] = ldcg_u32(hhc + o0 + kb + 16);
            ah[jj][3] = ldcg_u32(hhc + o8 + kb + 16);
        }
#pragma unroll
        for (int jj = 0; jj < 8; jj++) {
            uint32_t kb = kb0 + (uint32_t)jj * 32;
            al[jj][0] = ldcg_u32(hlc + o0 + kb);
            al[jj][1] = ldcg_u32(hlc + o8 + kb);
            al[jj][2] = ldcg_u32(hlc + o0 + kb + 16);
            al[jj][3] = ldcg_u32(hlc + o8 + kb + 16);
        }

        float a0e[4] = {}, a0o[4] = {}, a1e[4] = {}, a1o[4] = {};
        // pass 1: hhi x Whi, pass 2: hhi x Wlo
#pragma unroll
        for (int jj = 0; jj < 8; jj++) {
            if (jj & 1) {
                mma16816(a0o, ah[jj], wh[jj][0], wh[jj][1]);
                mma16816(a1o, ah[jj], wh[jj][2], wh[jj][3]);
            } else {
                mma16816(a0e, ah[jj], wh[jj][0], wh[jj][1]);
                mma16816(a1e, ah[jj], wh[jj][2], wh[jj][3]);
            }
        }
#pragma unroll
        for (int jj = 0; jj < 8; jj++) {
            if (jj & 1) {
                mma16816(a0o, ah[jj], wl[jj][0], wl[jj][1]);
                mma16816(a1o, ah[jj], wl[jj][2], wl[jj][3]);
            } else {
                mma16816(a0e, ah[jj], wl[jj][0], wl[jj][1]);
                mma16816(a1e, ah[jj], wl[jj][2], wl[jj][3]);
            }
        }
        // pass 3: hlo x Whi
#pragma unroll
        for (int jj = 0; jj < 8; jj++) {
            if (jj & 1) {
                mma16816(a0o, al[jj], wh[jj][0], wh[jj][1]);
                mma16816(a1o, al[jj], wh[jj][2], wh[jj][3]);
            } else {
                mma16816(a0e, al[jj], wh[jj][0], wh[jj][1]);
                mma16816(a1e, al[jj], wh[jj][2], wh[jj][3]);
            }
        }

        float* rw = red + wid * 288;
        rw[crow * 18 + ccol]           = a0e[0] + a0o[0];
        rw[crow * 18 + ccol + 1]       = a0e[1] + a0o[1];
        rw[(crow + 8) * 18 + ccol]     = a0e[2] + a0o[2];
        rw[(crow + 8) * 18 + ccol + 1] = a0e[3] + a0o[3];
        rw[crow * 18 + 8 + ccol]           = a1e[0] + a1o[0];
        rw[crow * 18 + 8 + ccol + 1]       = a1e[1] + a1o[1];
        rw[(crow + 8) * 18 + 8 + ccol]     = a1e[2] + a1o[2];
        rw[(crow + 8) * 18 + 8 + ccol + 1] = a1e[3] + a1o[3];
        __syncthreads();

        float v = gval;
#pragma unroll
        for (int w = 0; w < 8; w++) v += red[w * 288 + rb * 18 + rn];
        float hv = tanhf(v);
        __nv_bfloat16 hi = __float2bfloat16(hv);
        __nv_bfloat16 lo = __float2bfloat16(hv - __bfloat162float(hi));
        const int nxt = cur ^ 1;
        const int idx = rb * Hh + n0 + rn;
        g_Hhi[nxt][idx] = hi;
        g_Hlo[nxt][idx] = lo;
        if (s == Ss - 1) {
            g_A8[((size_t)s * Bb + rb) * Hh + n0 + rn] = to_e4m3(hv * ASCALE);
            out[(size_t)Bb * Ss * Vv + idx] = hv;
            __syncthreads();
            if (tid == 0)
                st_release(&g_flags[blockIdx.x * 32], base + (unsigned)(s + 1));
        } else {
            __syncthreads();
            if (tid == 0)
                st_release(&g_flags[blockIdx.x * 32], base + (unsigned)(s + 1));
            // deferred: ordered by the release of step s+2 (dec waits flag 8x+9)
            g_A8[((size_t)s * Bb + rb) * Hh + n0 + rn] = to_e4m3(hv * ASCALE);
        }
    }
}

// ---- dec role ----
__device__ void dec_load_stage(uint32_t sb, int stg, int ki, int bm, int bn, int tid) {
    uint32_t base = sb + stg * DEC_STG;
    const uint8_t* gA = g_A8 + (size_t)bm * 1024 + ki * 128;
    const uint8_t* gB = g_B8 + (size_t)bn * 1024 + ki * 128;
#pragma unroll
    for (int i = 0; i < 4; i++) {
        int c = tid + i * 256;
        int r = c >> 3, cc = c & 7;
        cp_async16(base + r * 128 + (((cc ^ (r & 7)) & 7) << 4),
                   gA + (size_t)r * 1024 + cc * 16);
    }
#pragma unroll
    for (int i = 0; i < 8; i++) {
        int c = tid + i * 256;
        int r = c >> 3, cc = c & 7;
        cp_async16(base + DEC_ASZ + r * 128 + (((cc ^ (r & 7)) & 7) << 4),
                   gB + (size_t)r * 1024 + cc * 16);
    }
}

__device__ void dec_tile(uint32_t sb, int bm, int bn, const float* __restrict__ b_dec,
                         const int* __restrict__ stop, float* __restrict__ out) {
    const int tid = threadIdx.x;
    const int wid = tid >> 5;
    const int lane = tid & 31;
    const int wm = wid & 1;
    const int wn = wid >> 1;

    float acc[4][8][4];
#pragma unroll
    for (int i = 0; i < 4; i++)
#pragma unroll
        for (int j = 0; j < 8; j++)
#pragma unroll
            for (int q = 0; q < 4; q++) acc[i][j][q] = 0.f;

    const int arow = wm * 64 + (lane & 15);
    const int ach = lane >> 4;
    const int as = arow & 7;
    const int brow = wn * 64 + ((lane >> 4) << 3) + (lane & 7);
    const int bch = (lane >> 3) & 1;
    const int bs = brow & 7;

    dec_load_stage(sb, 0, 0, bm, bn, tid); cp_commit();
    dec_load_stage(sb, 1, 1, bm, bn, tid); cp_commit();

    for (int ki = 0; ki < 8; ki++) {
        const int cur = ki % 3;
        if (ki + 2 < 8) {
            dec_load_stage(sb, (ki + 2) % 3, ki + 2, bm, bn, tid); cp_commit();
            asm volatile("cp.async.wait_group 2;" ::: "memory");
        } else if (ki + 1 < 8) {
            asm volatile("cp.async.wait_group 1;" ::: "memory");
        } else {
            asm volatile("cp.async.wait_group 0;" ::: "memory");
        }
        __syncthreads();

        const uint32_t aB = sb + cur * DEC_STG + arow * 128;
        const uint32_t bB = sb + cur * DEC_STG + DEC_ASZ + brow * 128;
#pragma unroll
        for (int kt = 0; kt < 4; kt++) {
            uint32_t af[4][4], bf[4][4];
            const uint32_t acs = ((uint32_t)((kt * 2 + ach) ^ as)) << 4;
            const uint32_t bcs = ((uint32_t)((kt * 2 + bch) ^ bs)) << 4;
#pragma unroll
            for (int mi = 0; mi < 4; mi++) ldsm4(af[mi], aB + mi * 2048 + acs);
#pragma unroll
            for (int ni2 = 0; ni2 < 4; ni2++) ldsm4(bf[ni2], bB + ni2 * 2048 + bcs);
#pragma unroll
            for (int mi = 0; mi < 4; mi++)
#pragma unroll
                for (int ni = 0; ni < 8; ni++)
                    mma16832f8(acc[mi][ni], af[mi], bf[ni >> 1][(ni & 1) * 2],
                               bf[ni >> 1][(ni & 1) * 2 + 1]);
        }
        __syncthreads();
    }

    const float SC = 1.0f / (ASCALE * BSCALE);
    int orow0[4];
    float msk0[4], msk1[4];
#pragma unroll
    for (int mi = 0; mi < 4; mi++) {
        int m0 = bm + wm * 64 + mi * 16 + (lane >> 2);
        orow0[mi] = (m0 & 15) * 128 + (m0 >> 4);
        msk0[mi] = (stop[orow0[mi]] == 0) ? 1.0f : 0.0f;
        msk1[mi] = (stop[orow0[mi] + 1024] == 0) ? 1.0f : 0.0f;
    }
#pragma unroll
    for (int ni = 0; ni < 8; ni++) {
        int n0 = bn + wn * 64 + ni * 8 + (lane & 3) * 2;
        float2 bd = *(const float2*)(b_dec + n0);
        float2 tp = *(const float2*)(g_topic + n0);
#pragma unroll
        for (int mi = 0; mi < 4; mi++) {
            float2 o0, o1;
            o0.x = acc[mi][ni][0] * SC + bd.x + tp.x * msk0[mi];
            o0.y = acc[mi][ni][1] * SC + bd.y + tp.y * msk0[mi];
            o1.x = acc[mi][ni][2] * SC + bd.x + tp.x * msk1[mi];
            o1.y = acc[mi][ni][3] * SC + bd.y + tp.y * msk1[mi];
            *(float2*)(out + (size_t)orow0[mi] * Vv + n0) = o0;
            *(float2*)(out + (size_t)(orow0[mi] + 1024) * Vv + n0) = o1;
        }
    }
}

__device__ void dec_role(char* dsm, const float* __restrict__ W_dec,
                         const float* __restrict__ b_dec,
                         const int* __restrict__ stop, float* __restrict__ out,
                         unsigned base, bool do_conv) {
    __shared__ int s_t;
    const int tid = threadIdx.x;
    uint32_t sb = (smem_u32(dsm) + 1023) & ~1023u;

    if (do_conv) {
        // convert W_dec -> fp8 in the shadow of rnn's first steps (84 CTAs)
        size_t n4 = (size_t)Vv * 1024 / 4;
        for (size_t i = (size_t)(blockIdx.x - RNN_NB) * 256 + tid; i < n4;
             i += (size_t)(CMB_NB - RNN_NB) * 256) {
            float4 v = ((const float4*)W_dec)[i];
            uchar4 o;
            o.x = to_e4m3(v.x * BSCALE);
            o.y = to_e4m3(v.y * BSCALE);
            o.z = to_e4m3(v.z * BSCALE);
            o.w = to_e4m3(v.w * BSCALE);
            ((uchar4*)g_B8)[i] = o;
        }
        __threadfence();
        __syncthreads();
        if (tid == 0) atomicAdd(&g_conv, 1u);
    }
    // wait for B conversion to complete (instant for late joiners)
    if (tid == 0) {
        while (ld_relaxed(&g_conv) < (unsigned)(CMB_NB - RNN_NB)) __nanosleep(512);
        (void)ld_acquire(&g_conv);
    }
    __syncthreads();

    for (;;) {
        if (tid == 0) s_t = (int)atomicAdd(&g_tile, 1u);
        __syncthreads();
        int t = s_t;
        if (t >= N_TILES) return;
        int x = t / 125;
        int y = t - x * 125;
        unsigned nv = (x == 15) ? 128u : (unsigned)(x * 8 + 9);
        unsigned need = base + nv;
        if (tid < RNN_NB) {
            const unsigned* fp = &g_flags[tid * 32];
            while (ld_relaxed(fp) < need) __nanosleep(1024);
            (void)ld_acquire(fp);
        }
        __syncthreads();
        dec_tile(sb, x * 128, y * 256, b_dec, stop, out);
        __syncthreads();
    }
}

__global__ __launch_bounds__(256, 1) void fused_kernel(const float* __restrict__ W_hh,
                                                       const float* __restrict__ W_dec,
                                                       const float* __restrict__ b_dec,
                                                       const int* __restrict__ stop,
                                                       float* __restrict__ out) {
    extern __shared__ __align__(16) char fsm[];
    const unsigned base = g_epoch << 8;
    if (blockIdx.x < RNN_NB) {
        rnn_role(fsm, W_hh, out, base);
        __syncthreads();
        dec_role(fsm, W_dec, b_dec, stop, out, base, false);
    } else {
        dec_role(fsm, W_dec, b_dec, stop, out, base, true);
    }
}

// ------------------------- launch -------------------------
extern "C" void kernel_launch(void* const* d_in, const int* in_sizes, int n_in,
                              void* d_out, int out_size) {
    const int*   input_ids = (const int*)d_in[0];
    const float* hidden    = (const float*)d_in[1];
    const int*   stop      = (const int*)d_in[2];
    const float* W_emb     = (const float*)d_in[3];
    const float* W_ih      = (const float*)d_in[4];
    const float* b_ih      = (const float*)d_in[5];
    const float* W_hh      = (const float*)d_in[6];
    const float* b_hh      = (const float*)d_in[7];
    const float* W_dec     = (const float*)d_in[8];
    const float* b_dec     = (const float*)d_in[9];
    const float* beta      = (const float*)d_in[10];
    const float* theta     = (const float*)d_in[11];
    float* out = (float*)d_out;

    cudaFuncSetAttribute(fused_kernel, cudaFuncAttributeMaxDynamicSharedMemorySize,
                         FUSED_SMEM);
    cudaFuncSetAttribute(embed_gemm, cudaFuncAttributeMaxDynamicSharedMemorySize,
                         EMB_SMEM);

    static cudaStream_t sB = nullptr;
    static cudaEvent_t eF = nullptr, eB = nullptr;
    if (sB == nullptr) {
        cudaStreamCreateWithFlags(&sB, cudaStreamNonBlocking);
        cudaEventCreateWithFlags(&eF, cudaEventDisableTiming);
        cudaEventCreateWithFlags(&eB, cudaEventDisableTiming);
    }

    // pre-phase fork: topic+init on sB; embed chain on main (convB folded into fused)
    cudaEventRecord(eF, 0);
    cudaStreamWaitEvent(sB, eF, 0);
    topic_kernel<<<(Vv + 255) / 256, 256, 0, sB>>>(beta, theta);
    init_h_kernel<<<(Bb * Hh + 255) / 256, 256, 0, sB>>>(hidden);
    convA_emb_kernel<<<(2048 * Ee) / 256, 256>>>(input_ids, W_emb);
    convWih_kernel<<<(Hh * Ee) / 256, 256>>>(W_ih);
    embed_gemm<<<dim3(16, 8), 256, EMB_SMEM>>>(b_ih, b_hh);
    cudaEventRecord(eB, sB);
    cudaStreamWaitEvent(0, eB, 0);

    // fused rnn + decoder (all 148 CTAs co-resident; writes ALL of out)
    fused_kernel<<<CMB_NB, 256, FUSED_SMEM>>>(W_hh, W_dec, b_dec, stop, out);
}

// round 17
// speedup vs baseline: 1.2429x; 1.2429x over previous
#include <cuda_runtime.h>
#include <cuda_bf16.h>
#include <cuda_fp8.h>
#include <math.h>
#include <stdint.h>

#define Vv 32000
#define Ee 512
#define Hh 1024
#define Bb 16
#define Ss 128
#define Kk 15

#define ASCALE 128.0f
#define BSCALE 256.0f

// ------------------------- device scratch (no allocs allowed) -------------------------
__device__ float g_G[Ss * Bb * Hh];               // [s][b][h]
__device__ __nv_bfloat16 g_Hhi[2][Bb * Hh];
__device__ __nv_bfloat16 g_Hlo[2][Bb * Hh];
__device__ float g_topic[Vv];
__device__ unsigned g_epoch;                      // bumped each launch (init_h)
__device__ unsigned g_flags[64 * 32];             // per-rnn-CTA flag, 1 per 128B line
__device__ unsigned g_tile;                       // dec tile queue head (reset each launch)
// fp8 decoder operands
__device__ uint8_t g_A8[2048 * 1024];             // [m = s*16+b][k]  (h * 128, e4m3)
__device__ uint8_t g_B8[(size_t)Vv * 1024];       // [v][k]           (W_dec * 256, e4m3)
// pre-split bf16 operands for embed GEMM
__device__ __nv_bfloat16 g_EAhi[2048 * Ee];
__device__ __nv_bfloat16 g_EAlo[2048 * Ee];
__device__ __nv_bfloat16 g_EBhi[Hh * Ee];
__device__ __nv_bfloat16 g_EBlo[Hh * Ee];

// ------------------------- PTX helpers -------------------------
__device__ __forceinline__ uint32_t smem_u32(const void* p) {
    uint32_t a;
    asm("{ .reg .u64 t; cvta.to.shared.u64 t, %1; cvt.u32.u64 %0, t; }" : "=r"(a) : "l"(p));
    return a;
}
__device__ __forceinline__ void cp_async16(uint32_t dst, const void* src) {
    asm volatile("cp.async.cg.shared.global [%0], [%1], 16;" :: "r"(dst), "l"(src) : "memory");
}
__device__ __forceinline__ void cp_commit() { asm volatile("cp.async.commit_group;" ::: "memory"); }

__device__ __forceinline__ void ldsm4(uint32_t* r, uint32_t addr) {
    asm volatile("ldmatrix.sync.aligned.m8n8.x4.shared.b16 {%0,%1,%2,%3}, [%4];"
                 : "=r"(r[0]), "=r"(r[1]), "=r"(r[2]), "=r"(r[3]) : "r"(addr));
}
__device__ __forceinline__ void mma16816(float* c, const uint32_t* a, uint32_t b0, uint32_t b1) {
    asm volatile("mma.sync.aligned.m16n8k16.row.col.f32.bf16.bf16.f32 "
                 "{%0,%1,%2,%3}, {%4,%5,%6,%7}, {%8,%9}, {%0,%1,%2,%3};"
                 : "+f"(c[0]), "+f"(c[1]), "+f"(c[2]), "+f"(c[3])
                 : "r"(a[0]), "r"(a[1]), "r"(a[2]), "r"(a[3]), "r"(b0), "r"(b1));
}
__device__ __forceinline__ void mma16832f8(float* c, const uint32_t* a, uint32_t b0, uint32_t b1) {
    asm volatile("mma.sync.aligned.m16n8k32.row.col.f32.e4m3.e4m3.f32 "
                 "{%0,%1,%2,%3}, {%4,%5,%6,%7}, {%8,%9}, {%0,%1,%2,%3};"
                 : "+f"(c[0]), "+f"(c[1]), "+f"(c[2]), "+f"(c[3])
                 : "r"(a[0]), "r"(a[1]), "r"(a[2]), "r"(a[3]), "r"(b0), "r"(b1));
}
__device__ __forceinline__ uint8_t to_e4m3(float x) {
    return (uint8_t)__nv_cvt_float_to_fp8(x, __NV_SATFINITE, __NV_E4M3);
}
__device__ __forceinline__ void st_release(unsigned* p, unsigned v) {
    asm volatile("st.release.gpu.global.u32 [%0], %1;" :: "l"(p), "r"(v) : "memory");
}
__device__ __forceinline__ unsigned ld_relaxed(const unsigned* p) {
    unsigned v;
    asm volatile("ld.relaxed.gpu.global.u32 %0, [%1];" : "=r"(v) : "l"(p));
    return v;
}
__device__ __forceinline__ unsigned ld_acquire(const unsigned* p) {
    unsigned v;
    asm volatile("ld.acquire.gpu.global.u32 %0, [%1];" : "=r"(v) : "l"(p) : "memory");
    return v;
}

// ------------------------- tiny kernels -------------------------
__global__ void topic_kernel(const float* __restrict__ beta, const float* __restrict__ theta) {
    int v = blockIdx.x * 256 + threadIdx.x;
    if (v < Vv) {
        float s = 0.f;
#pragma unroll
        for (int k = 0; k < Kk; k++) s += theta[k] * beta[k * Vv + v];
        g_topic[v] = s;
    }
}
__global__ void init_h_kernel(const float* __restrict__ hidden) {
    int i = blockIdx.x * 256 + threadIdx.x;
    if (i < Bb * Hh) {
        float x = hidden[i];
        __nv_bfloat16 hi = __float2bfloat16(x);
        g_Hhi[0][i] = hi;
        g_Hlo[0][i] = __float2bfloat16(x - __bfloat162float(hi));
    }
    if (i == 0) { g_epoch = g_epoch + 1; g_tile = 0; }
}
__global__ void convB_kernel(const float* __restrict__ W_dec) {
    size_t i = (size_t)blockIdx.x * 256 + threadIdx.x;   // float4 groups
    float4 v = ((const float4*)W_dec)[i];
    uchar4 o;
    o.x = to_e4m3(v.x * BSCALE);
    o.y = to_e4m3(v.y * BSCALE);
    o.z = to_e4m3(v.z * BSCALE);
    o.w = to_e4m3(v.w * BSCALE);
    ((uchar4*)g_B8)[i] = o;
}
// gather + split W_emb rows -> EA slabs
__global__ void convA_emb_kernel(const int* __restrict__ ids,
                                 const float* __restrict__ W_emb) {
    int i = blockIdx.x * 256 + threadIdx.x;   // 2048*512
    int m = i >> 9, k = i & 511;
    int row = ids[(m & 15) * Ss + (m >> 4)];
    float x = W_emb[(size_t)row * Ee + k];
    __nv_bfloat16 hi = __float2bfloat16(x);
    g_EAhi[i] = hi;
    g_EAlo[i] = __float2bfloat16(x - __bfloat162float(hi));
}
// split W_ih -> EB slabs
__global__ void convWih_kernel(const float* __restrict__ W_ih) {
    int i = blockIdx.x * 256 + threadIdx.x;   // 1024*512
    float x = W_ih[i];
    __nv_bfloat16 hi = __float2bfloat16(x);
    g_EBhi[i] = hi;
    g_EBlo[i] = __float2bfloat16(x - __bfloat162float(hi));
}

// ------------------------- embed GEMM: pipelined bf16, 3-term K-concat ---------------
#define EMB_ASZ 16384
#define EMB_BSZ 16384
#define EMB_STG (EMB_ASZ + EMB_BSZ)
#define EMB_SMEM (3 * EMB_STG + 1024)

__device__ __forceinline__ void emb_load_stage(uint32_t sb, int stg, int ki,
                                               int bm, int bn, int tid) {
    const int t = ki >> 3, kc = ki & 7;
    const __nv_bfloat16* sA = (t == 1) ? g_EAlo : g_EAhi;
    const __nv_bfloat16* sB = (t == 2) ? g_EBlo : g_EBhi;
    const __nv_bfloat16* gA = sA + (size_t)bm * Ee + kc * 64;
    const __nv_bfloat16* gB = sB + (size_t)bn * Ee + kc * 64;
    uint32_t base = sb + stg * EMB_STG;
#pragma unroll
    for (int i = 0; i < 4; i++) {
        int c = tid + i * 256;
        int r = c >> 3, cc = c & 7;
        cp_async16(base + r * 128 + (((cc ^ (r & 7)) & 7) << 4),
                   gA + (size_t)r * Ee + cc * 8);
    }
#pragma unroll
    for (int i = 0; i < 4; i++) {
        int c = tid + i * 256;
        int r = c >> 3, cc = c & 7;
        cp_async16(base + EMB_ASZ + r * 128 + (((cc ^ (r & 7)) & 7) << 4),
                   gB + (size_t)r * Ee + cc * 8);
    }
}

__global__ __launch_bounds__(256, 1) void embed_gemm(const float* __restrict__ b_ih,
                                                     const float* __restrict__ b_hh) {
    extern __shared__ __align__(16) char esm[];
    const int tid = threadIdx.x;
    const int wid = tid >> 5;
    const int lane = tid & 31;
    const int wm = wid & 1;
    const int wn = wid >> 1;
    const int bm = blockIdx.x * 128;
    const int bn = blockIdx.y * 128;
    uint32_t sb = (smem_u32(esm) + 1023) & ~1023u;

    float acc[4][4][4];
#pragma unroll
    for (int i = 0; i < 4; i++)
#pragma unroll
        for (int j = 0; j < 4; j++)
#pragma unroll
            for (int q = 0; q < 4; q++) acc[i][j][q] = 0.f;

    const int arow = wm * 64 + (lane & 15);
    const int ach = lane >> 4;
    const int as = arow & 7;
    const int brow = wn * 32 + ((lane >> 4) << 3) + (lane & 7);
    const int bch = (lane >> 3) & 1;
    const int bs = brow & 7;

    emb_load_stage(sb, 0, 0, bm, bn, tid); cp_commit();
    emb_load_stage(sb, 1, 1, bm, bn, tid); cp_commit();

    for (int ki = 0; ki < 24; ki++) {
        const int cur = ki % 3;
        if (ki + 2 < 24) {
            emb_load_stage(sb, (ki + 2) % 3, ki + 2, bm, bn, tid); cp_commit();
            asm volatile("cp.async.wait_group 2;" ::: "memory");
        } else if (ki + 1 < 24) {
            asm volatile("cp.async.wait_group 1;" ::: "memory");
        } else {
            asm volatile("cp.async.wait_group 0;" ::: "memory");
        }
        __syncthreads();

        const uint32_t aB = sb + cur * EMB_STG + arow * 128;
        const uint32_t bB = sb + cur * EMB_STG + EMB_ASZ + brow * 128;
#pragma unroll
        for (int k16 = 0; k16 < 4; k16++) {
            uint32_t af[4][4], bf[2][4];
            const uint32_t acs = ((uint32_t)((k16 * 2 + ach) ^ as)) << 4;
            const uint32_t bcs = ((uint32_t)((k16 * 2 + bch) ^ bs)) << 4;
#pragma unroll
            for (int mi = 0; mi < 4; mi++) ldsm4(af[mi], aB + mi * 2048 + acs);
#pragma unroll
            for (int ni2 = 0; ni2 < 2; ni2++) ldsm4(bf[ni2], bB + ni2 * 2048 + bcs);
#pragma unroll
            for (int mi = 0; mi < 4; mi++)
#pragma unroll
                for (int ni = 0; ni < 4; ni++)
                    mma16816(acc[mi][ni], af[mi], bf[ni >> 1][(ni & 1) * 2],
                             bf[ni >> 1][(ni & 1) * 2 + 1]);
        }
        __syncthreads();
    }

#pragma unroll
    for (int ni = 0; ni < 4; ni++) {
        int n0 = bn + wn * 32 + ni * 8 + (lane & 3) * 2;
        float2 bi = *(const float2*)(b_ih + n0);
        float2 bh = *(const float2*)(b_hh + n0);
        float2 bb = make_float2(bi.x + bh.x, bi.y + bh.y);
#pragma unroll
        for (int mi = 0; mi < 4; mi++) {
            int m0 = bm + wm * 64 + mi * 16 + (lane >> 2);
            float2 o0 = make_float2(acc[mi][ni][0] + bb.x, acc[mi][ni][1] + bb.y);
            float2 o1 = make_float2(acc[mi][ni][2] + bb.x, acc[mi][ni][3] + bb.y);
            *(float2*)(g_G + (size_t)m0 * Hh + n0) = o0;
            *(float2*)(g_G + (size_t)(m0 + 8) * Hh + n0) = o1;
        }
    }
}

// ------------------------- fused persistent kernel: rnn + dec -------------------------
#define RNN_NB 64
#define CMB_NB 148
#define N_TILES (16 * 125)
#define WHI_OFF 0
#define WLO_OFF 32768
#define HHI_OFF 65536
#define HLO_OFF 98304
#define RNN_RED_OFF 131072
#define DEC_ASZ 16384
#define DEC_BSZ 32768
#define DEC_STG (DEC_ASZ + DEC_BSZ)
#define FUSED_SMEM (3 * DEC_STG + 1024)

// ---- rnn role: per-warp dataflow, W fragments hoisted into registers ----
__device__ void rnn_role(char* rsm, const float* __restrict__ W_hh,
                         float* __restrict__ out, unsigned base) {
    float* red = (float*)(rsm + RNN_RED_OFF);
    const int tid = threadIdx.x;
    const int wid = tid >> 5;
    const int lane = tid & 31;
    const int n0 = blockIdx.x * 16;

    // build W hi/lo slabs in SMEM (once)
#pragma unroll
    for (int i = 0; i < 8; i++) {
        int c = tid + i * 256;
        int r = c >> 7, kc = c & 127;
        const float* src = W_hh + (size_t)(n0 + r) * Hh + kc * 8;
        float4 v0 = *(const float4*)src;
        float4 v1 = *(const float4*)(src + 4);
        float x[8] = {v0.x, v0.y, v0.z, v0.w, v1.x, v1.y, v1.z, v1.w};
        __nv_bfloat16 hi[8], lo[8];
#pragma unroll
        for (int q = 0; q < 8; q++) {
            hi[q] = __float2bfloat16(x[q]);
            lo[q] = __float2bfloat16(x[q] - __bfloat162float(hi[q]));
        }
        uint32_t off = r * 2048 + (((kc ^ (r & 7)) & 127) << 4);
        *(uint4*)(rsm + WHI_OFF + off) = *(uint4*)hi;
        *(uint4*)(rsm + WLO_OFF + off) = *(uint4*)lo;
    }
    __syncthreads();

    const int arow = lane & 15;
    const int ach = lane >> 4;
    const int brow = ((lane >> 4) << 3) + (lane & 7);
    const int bch = (lane >> 3) & 1;
    const int crow = lane >> 2, ccol = (lane & 3) * 2;
    const int rb = tid >> 4, rn = tid & 15;
    const uint32_t smb = smem_u32(rsm);
    const unsigned* wfp = &g_flags[(wid * 8 + (lane & 7)) * 32];

    // preload W fragments into registers (loop-invariant; 64 regs)
    uint32_t wh[8][4], wl[8][4];
#pragma unroll
    for (int jj = 0; jj < 8; jj++) {
        int cj = (wid * 8 + jj) * 2;
        uint32_t sw = ((((cj + bch) ^ (brow & 7)) & 127) << 4);
        ldsm4(wh[jj], smb + WHI_OFF + brow * 2048 + sw);
        ldsm4(wl[jj], smb + WLO_OFF + brow * 2048 + sw);
    }

    for (int s = 0; s < Ss; s++) {
        const int cur = s & 1;
        float gval = __ldcg(&g_G[(size_t)s * (Bb * Hh) + rb * Hh + n0 + rn]);

        if (s > 0) {
            if (lane < 8) {
                unsigned need = base + (unsigned)s;
                while (ld_relaxed(wfp) < need) { }
                (void)ld_acquire(wfp);
            }
            __syncwarp();
        }

        // per-warp staging: hhi group, then hlo group (proven cp.async path)
        const __nv_bfloat16* hh = g_Hhi[cur];
        const __nv_bfloat16* hl = g_Hlo[cur];
#pragma unroll
        for (int l = 0; l < 8; l++) {
            int c = l * 32 + lane;
            int r = c >> 4;
            int kc = wid * 16 + (c & 15);
            uint32_t off = r * 2048 + (((kc ^ (r & 7)) & 127) << 4);
            cp_async16(smb + HHI_OFF + off, hh + r * Hh + kc * 8);
        }
        cp_commit();
#pragma unroll
        for (int l = 0; l < 8; l++) {
            int c = l * 32 + lane;
            int r = c >> 4;
            int kc = wid * 16 + (c & 15);
            uint32_t off = r * 2048 + (((kc ^ (r & 7)) & 127) << 4);
            cp_async16(smb + HLO_OFF + off, hl + r * Hh + kc * 8);
        }
        cp_commit();

        float a0e[4] = {}, a0o[4] = {}, a1e[4] = {}, a1o[4] = {};
        asm volatile("cp.async.wait_group 1;" ::: "memory");   // hhi ready
        __syncwarp();
        // hhi pass: each a-frag feeds BOTH Whi and Wlo mmas (loaded once)
#pragma unroll
        for (int jj = 0; jj < 8; jj++) {
            int cj = (wid * 8 + jj) * 2;
            uint32_t af[4];
            ldsm4(af, smb + HHI_OFF + arow * 2048 +
                      ((((cj + ach) ^ (arow & 7)) & 127) << 4));
            if (jj & 1) {
                mma16816(a0o, af, wh[jj][0], wh[jj][1]);
                mma16816(a1o, af, wh[jj][2], wh[jj][3]);
                mma16816(a0o, af, wl[jj][0], wl[jj][1]);
                mma16816(a1o, af, wl[jj][2], wl[jj][3]);
            } else {
                mma16816(a0e, af, wh[jj][0], wh[jj][1]);
                mma16816(a1e, af, wh[jj][2], wh[jj][3]);
                mma16816(a0e, af, wl[jj][0], wl[jj][1]);
                mma16816(a1e, af, wl[jj][2], wl[jj][3]);
            }
        }
        asm volatile("cp.async.wait_group 0;" ::: "memory");   // hlo ready
        __syncwarp();
        // hlo pass: x Whi
#pragma unroll
        for (int jj = 0; jj < 8; jj++) {
            int cj = (wid * 8 + jj) * 2;
            uint32_t af[4];
            ldsm4(af, smb + HLO_OFF + arow * 2048 +
                      ((((cj + ach) ^ (arow & 7)) & 127) << 4));
            if (jj & 1) {
                mma16816(a0o, af, wh[jj][0], wh[jj][1]);
                mma16816(a1o, af, wh[jj][2], wh[jj][3]);
            } else {
                mma16816(a0e, af, wh[jj][0], wh[jj][1]);
                mma16816(a1e, af, wh[jj][2], wh[jj][3]);
            }
        }

        float* rw = red + wid * 288;
        rw[crow * 18 + ccol]           = a0e[0] + a0o[0];
        rw[crow * 18 + ccol + 1]       = a0e[1] + a0o[1];
        rw[(crow + 8) * 18 + ccol]     = a0e[2] + a0o[2];
        rw[(crow + 8) * 18 + ccol + 1] = a0e[3] + a0o[3];
        rw[crow * 18 + 8 + ccol]           = a1e[0] + a1o[0];
        rw[crow * 18 + 8 + ccol + 1]       = a1e[1] + a1o[1];
        rw[(crow + 8) * 18 + 8 + ccol]     = a1e[2] + a1o[2];
        rw[(crow + 8) * 18 + 8 + ccol + 1] = a1e[3] + a1o[3];
        __syncthreads();

        float v = gval;
#pragma unroll
        for (int w = 0; w < 8; w++) v += red[w * 288 + rb * 18 + rn];
        float hv = tanhf(v);
        __nv_bfloat16 hi = __float2bfloat16(hv);
        __nv_bfloat16 lo = __float2bfloat16(hv - __bfloat162float(hi));
        const int nxt = cur ^ 1;
        const int idx = rb * Hh + n0 + rn;
        g_Hhi[nxt][idx] = hi;
        g_Hlo[nxt][idx] = lo;
        if (s == Ss - 1) {
            g_A8[((size_t)s * Bb + rb) * Hh + n0 + rn] = to_e4m3(hv * ASCALE);
            out[(size_t)Bb * Ss * Vv + idx] = hv;
            __syncthreads();
            if (tid == 0)
                st_release(&g_flags[blockIdx.x * 32], base + (unsigned)(s + 1));
        } else {
            __syncthreads();
            if (tid == 0)
                st_release(&g_flags[blockIdx.x * 32], base + (unsigned)(s + 1));
            // deferred: ordered by the release of step s+2 (dec waits flag 8x+9)
            g_A8[((size_t)s * Bb + rb) * Hh + n0 + rn] = to_e4m3(hv * ASCALE);
        }
    }
}

// ---- dec role ----
__device__ void dec_load_stage(uint32_t sb, int stg, int ki, int bm, int bn, int tid) {
    uint32_t base = sb + stg * DEC_STG;
    const uint8_t* gA = g_A8 + (size_t)bm * 1024 + ki * 128;
    const uint8_t* gB = g_B8 + (size_t)bn * 1024 + ki * 128;
#pragma unroll
    for (int i = 0; i < 4; i++) {
        int c = tid + i * 256;
        int r = c >> 3, cc = c & 7;
        cp_async16(base + r * 128 + (((cc ^ (r & 7)) & 7) << 4),
                   gA + (size_t)r * 1024 + cc * 16);
    }
#pragma unroll
    for (int i = 0; i < 8; i++) {
        int c = tid + i * 256;
        int r = c >> 3, cc = c & 7;
        cp_async16(base + DEC_ASZ + r * 128 + (((cc ^ (r & 7)) & 7) << 4),
                   gB + (size_t)r * 1024 + cc * 16);
    }
}

__device__ void dec_tile(uint32_t sb, int bm, int bn, const float* __restrict__ b_dec,
                         const int* __restrict__ stop, float* __restrict__ out) {
    const int tid = threadIdx.x;
    const int wid = tid >> 5;
    const int lane = tid & 31;
    const int wm = wid & 1;
    const int wn = wid >> 1;

    float acc[4][8][4];
#pragma unroll
    for (int i = 0; i < 4; i++)
#pragma unroll
        for (int j = 0; j < 8; j++)
#pragma unroll
            for (int q = 0; q < 4; q++) acc[i][j][q] = 0.f;

    const int arow = wm * 64 + (lane & 15);
    const int ach = lane >> 4;
    const int as = arow & 7;
    const int brow = wn * 64 + ((lane >> 4) << 3) + (lane & 7);
    const int bch = (lane >> 3) & 1;
    const int bs = brow & 7;

    dec_load_stage(sb, 0, 0, bm, bn, tid); cp_commit();
    dec_load_stage(sb, 1, 1, bm, bn, tid); cp_commit();

    for (int ki = 0; ki < 8; ki++) {
        const int cur = ki % 3;
        if (ki + 2 < 8) {
            dec_load_stage(sb, (ki + 2) % 3, ki + 2, bm, bn, tid); cp_commit();
            asm volatile("cp.async.wait_group 2;" ::: "memory");
        } else if (ki + 1 < 8) {
            asm volatile("cp.async.wait_group 1;" ::: "memory");
        } else {
            asm volatile("cp.async.wait_group 0;" ::: "memory");
        }
        __syncthreads();

        const uint32_t aB = sb + cur * DEC_STG + arow * 128;
        const uint32_t bB = sb + cur * DEC_STG + DEC_ASZ + brow * 128;
#pragma unroll
        for (int kt = 0; kt < 4; kt++) {
            uint32_t af[4][4], bf[4][4];
            const uint32_t acs = ((uint32_t)((kt * 2 + ach) ^ as)) << 4;
            const uint32_t bcs = ((uint32_t)((kt * 2 + bch) ^ bs)) << 4;
#pragma unroll
            for (int mi = 0; mi < 4; mi++) ldsm4(af[mi], aB + mi * 2048 + acs);
#pragma unroll
            for (int ni2 = 0; ni2 < 4; ni2++) ldsm4(bf[ni2], bB + ni2 * 2048 + bcs);
#pragma unroll
            for (int mi = 0; mi < 4; mi++)
#pragma unroll
                for (int ni = 0; ni < 8; ni++)
                    mma16832f8(acc[mi][ni], af[mi], bf[ni >> 1][(ni & 1) * 2],
                               bf[ni >> 1][(ni & 1) * 2 + 1]);
        }
        __syncthreads();
    }

    const float SC = 1.0f / (ASCALE * BSCALE);
    int orow0[4];
    float msk0[4], msk1[4];
#pragma unroll
    for (int mi = 0; mi < 4; mi++) {
        int m0 = bm + wm * 64 + mi * 16 + (lane >> 2);
        orow0[mi] = (m0 & 15) * 128 + (m0 >> 4);
        msk0[mi] = (stop[orow0[mi]] == 0) ? 1.0f : 0.0f;
        msk1[mi] = (stop[orow0[mi] + 1024] == 0) ? 1.0f : 0.0f;
    }
#pragma unroll
    for (int ni = 0; ni < 8; ni++) {
        int n0 = bn + wn * 64 + ni * 8 + (lane & 3) * 2;
        float2 bd = *(const float2*)(b_dec + n0);
        float2 tp = *(const float2*)(g_topic + n0);
#pragma unroll
        for (int mi = 0; mi < 4; mi++) {
            float2 o0, o1;
            o0.x = acc[mi][ni][0] * SC + bd.x + tp.x * msk0[mi];
            o0.y = acc[mi][ni][1] * SC + bd.y + tp.y * msk0[mi];
            o1.x = acc[mi][ni][2] * SC + bd.x + tp.x * msk1[mi];
            o1.y = acc[mi][ni][3] * SC + bd.y + tp.y * msk1[mi];
            *(float2*)(out + (size_t)orow0[mi] * Vv + n0) = o0;
            *(float2*)(out + (size_t)(orow0[mi] + 1024) * Vv + n0) = o1;
        }
    }
}

__device__ void dec_role(char* dsm, const float* __restrict__ b_dec,
                         const int* __restrict__ stop, float* __restrict__ out,
                         unsigned base) {
    __shared__ int s_t;
    const int tid = threadIdx.x;
    uint32_t sb = (smem_u32(dsm) + 1023) & ~1023u;
    for (;;) {
        if (tid == 0) s_t = (int)atomicAdd(&g_tile, 1u);
        __syncthreads();
        int t = s_t;
        if (t >= N_TILES) return;
        int x = t / 125;
        int y = t - x * 125;
        unsigned nv = (x == 15) ? 128u : (unsigned)(x * 8 + 9);
        unsigned need = base + nv;
        if (tid < RNN_NB) {
            const unsigned* fp = &g_flags[tid * 32];
            while (ld_relaxed(fp) < need) __nanosleep(1024);
            (void)ld_acquire(fp);
        }
        __syncthreads();
        dec_tile(sb, x * 128, y * 256, b_dec, stop, out);
        __syncthreads();
    }
}

__global__ __launch_bounds__(256, 1) void fused_kernel(const float* __restrict__ W_hh,
                                                       const float* __restrict__ b_dec,
                                                       const int* __restrict__ stop,
                                                       float* __restrict__ out) {
    extern __shared__ __align__(16) char fsm[];
    const unsigned base = g_epoch << 8;
    if (blockIdx.x < RNN_NB) {
        rnn_role(fsm, W_hh, out, base);
        __syncthreads();
        dec_role(fsm, b_dec, stop, out, base);
    } else {
        dec_role(fsm, b_dec, stop, out, base);
    }
}

// ------------------------- launch -------------------------
extern "C" void kernel_launch(void* const* d_in, const int* in_sizes, int n_in,
                              void* d_out, int out_size) {
    const int*   input_ids = (const int*)d_in[0];
    const float* hidden    = (const float*)d_in[1];
    const int*   stop      = (const int*)d_in[2];
    const float* W_emb     = (const float*)d_in[3];
    const float* W_ih      = (const float*)d_in[4];
    const float* b_ih      = (const float*)d_in[5];
    const float* W_hh      = (const float*)d_in[6];
    const float* b_hh      = (const float*)d_in[7];
    const float* W_dec     = (const float*)d_in[8];
    const float* b_dec     = (const float*)d_in[9];
    const float* beta      = (const float*)d_in[10];
    const float* theta     = (const float*)d_in[11];
    float* out = (float*)d_out;

    cudaFuncSetAttribute(fused_kernel, cudaFuncAttributeMaxDynamicSharedMemorySize,
                         FUSED_SMEM);
    cudaFuncSetAttribute(embed_gemm, cudaFuncAttributeMaxDynamicSharedMemorySize,
                         EMB_SMEM);

    static cudaStream_t sA = nullptr, sB = nullptr;
    static cudaEvent_t eF = nullptr, eA = nullptr, eB = nullptr;
    if (sA == nullptr) {
        cudaStreamCreateWithFlags(&sA, cudaStreamNonBlocking);
        cudaStreamCreateWithFlags(&sB, cudaStreamNonBlocking);
        cudaEventCreateWithFlags(&eF, cudaEventDisableTiming);
        cudaEventCreateWithFlags(&eA, cudaEventDisableTiming);
        cudaEventCreateWithFlags(&eB, cudaEventDisableTiming);
    }

    // pre-phase fork: convB on sA; topic+init on sB; embed chain on main
    cudaEventRecord(eF, 0);
    cudaStreamWaitEvent(sA, eF, 0);
    cudaStreamWaitEvent(sB, eF, 0);
    convB_kernel<<<(int)(((size_t)Vv * 1024 / 4) / 256), 256, 0, sA>>>(W_dec);
    topic_kernel<<<(Vv + 255) / 256, 256, 0, sB>>>(beta, theta);
    init_h_kernel<<<(Bb * Hh + 255) / 256, 256, 0, sB>>>(hidden);
    convA_emb_kernel<<<(2048 * Ee) / 256, 256>>>(input_ids, W_emb);
    convWih_kernel<<<(Hh * Ee) / 256, 256>>>(W_ih);
    embed_gemm<<<dim3(16, 8), 256, EMB_SMEM>>>(b_ih, b_hh);
    cudaEventRecord(eA, sA);
    cudaEventRecord(eB, sB);
    cudaStreamWaitEvent(0, eA, 0);
    cudaStreamWaitEvent(0, eB, 0);

    // fused rnn + decoder (all 148 CTAs co-resident; writes ALL of out)
    fused_kernel<<<CMB_NB, 256, FUSED_SMEM>>>(W_hh, b_dec, stop, out);
}